// round 2
// baseline (speedup 1.0000x reference)
#include <cuda_runtime.h>
#include <cstdint>

// Problem constants
#define M_ROWS 16384      // 8 * 2048
#define D_IN   512
#define NB     8          // GRID_SIZE + SPLINE_ORDER
#define KTOT   4608       // 512 (relu base) + 512*8 (bs+rbf)
#define N_OUT  512

// Scratch (allocation-free rule: __device__ globals)
__device__ float g_F[(size_t)M_ROWS * KTOT];   // feature matrix, row-major [M][K]
__device__ float g_W[(size_t)N_OUT * KTOT];    // concat weights,  row-major [N][K]

// ---------------------------------------------------------------------------
// Kernel 0: build concatenated weight matrix W = [base_weight | spline_weight]
// ---------------------------------------------------------------------------
__global__ void prep_kernel(const float* __restrict__ bw,
                            const float* __restrict__ sw) {
    int o = blockIdx.x;           // 0..511
    int t = threadIdx.x;          // 256 threads
    for (int k = t; k < D_IN; k += 256)
        g_W[(size_t)o * KTOT + k] = bw[o * D_IN + k];
    const float4* s4 = (const float4*)(sw + (size_t)o * (D_IN * NB));
    float4*       d4 = (float4*)(g_W + (size_t)o * KTOT + D_IN);
    for (int k = t; k < (D_IN * NB) / 4; k += 256)
        d4[k] = s4[k];
}

// ---------------------------------------------------------------------------
// Kernel 1: per-row layernorm + feature generation
//   f[0:512]            = relu(xn)
//   f[512 + d*8 + j]    = bspline_j(xn_d) + exp(-((xn_d - g_j)/denom)^2)
// ---------------------------------------------------------------------------
__global__ void feat_kernel(const float* __restrict__ x,
                            const float* __restrict__ gamma,
                            const float* __restrict__ beta) {
    const int row = blockIdx.x;
    const int t   = threadIdx.x;        // 256 threads, 2 dims each
    const float* xr = x + (size_t)row * D_IN;

    float v0 = xr[t];
    float v1 = xr[t + 256];
    float s  = v0 + v1;
    float s2 = v0 * v0 + v1 * v1;
    #pragma unroll
    for (int off = 16; off; off >>= 1) {
        s  += __shfl_xor_sync(0xFFFFFFFFu, s,  off);
        s2 += __shfl_xor_sync(0xFFFFFFFFu, s2, off);
    }
    __shared__ float red[16];
    __shared__ float mu_s, rstd_s;
    int wid = t >> 5, lane = t & 31;
    if (lane == 0) { red[wid] = s; red[8 + wid] = s2; }
    __syncthreads();
    if (t == 0) {
        float ts = 0.f, ts2 = 0.f;
        #pragma unroll
        for (int i = 0; i < 8; i++) { ts += red[i]; ts2 += red[8 + i]; }
        float mu  = ts * (1.0f / 512.0f);
        float var = ts2 * (1.0f / 512.0f) - mu * mu;
        mu_s   = mu;
        rstd_s = rsqrtf(var + 1e-5f);
    }
    __syncthreads();
    const float mu = mu_s, rstd = rstd_s;

    float* Fr = g_F + (size_t)row * KTOT;
    const float H    = 3.0f / 5.0f;          // knot spacing
    const float INVD = 7.0f / 3.0f;          // 1/denom for RBF

    #pragma unroll
    for (int half = 0; half < 2; half++) {
        const int   d  = t + half * 256;
        const float xv = half ? v1 : v0;
        const float xn = (xv - mu) * rstd * gamma[d] + beta[d];

        Fr[d] = fmaxf(xn, 0.0f);

        // Cox-de Boor, uniform knots t_i = (i-3)*H - 1.5, i=0..11
        float b[11];
        #pragma unroll
        for (int i = 0; i < 11; i++) {
            float t0 = (float)(i - 3) * H - 1.5f;
            float t1 = (float)(i - 2) * H - 1.5f;
            b[i] = (xn >= t0 && xn < t1) ? 1.0f : 0.0f;
        }
        #pragma unroll
        for (int k = 1; k <= 3; k++) {
            const float inv = 1.0f / ((float)k * H);
            #pragma unroll
            for (int i = 0; i + k < 11; i++) {
                float ti   = (float)(i - 3) * H - 1.5f;
                float tik1 = (float)(i + k - 2) * H - 1.5f;   // t_{i+k+1}
                float left  = (xn - ti) * inv;
                float right = (tik1 - xn) * inv;
                b[i] = left * b[i] + right * b[i + 1];
            }
        }

        float out[8];
        #pragma unroll
        for (int j = 0; j < 8; j++) {
            float g = -1.5f + (float)j * (3.0f / 7.0f);
            float u = (xn - g) * INVD;
            out[j] = b[j] + __expf(-u * u);
        }
        float4* dst = (float4*)(Fr + D_IN + d * NB);
        dst[0] = make_float4(out[0], out[1], out[2], out[3]);
        dst[1] = make_float4(out[4], out[5], out[6], out[7]);
    }
}

// ---------------------------------------------------------------------------
// Kernel 2: C[M][N] = F[M][K] * W[N][K]^T, fp32
// 128x128x8 tile, 8x8 microtile, double-buffered shared memory
// ---------------------------------------------------------------------------
#define BM 128
#define BN 128
#define BK 8
#define SSTR 136   // padded shared row stride (floats)

__global__ __launch_bounds__(256, 2) void gemm_kernel(float* __restrict__ C) {
    __shared__ float As[2][BK][SSTR];
    __shared__ float Bs[2][BK][SSTR];

    const int t  = threadIdx.x;
    const int m0 = blockIdx.y * BM;
    const int n0 = blockIdx.x * BN;

    const int lr = t >> 1;          // 0..127: tile row this thread loads
    const int lk = (t & 1) * 4;     // 0 or 4: k sub-offset (float4)
    const float* Aptr = g_F + (size_t)(m0 + lr) * KTOT + lk;
    const float* Bptr = g_W + (size_t)(n0 + lr) * KTOT + lk;

    const int tx = t & 15;          // n micro-tile index
    const int ty = t >> 4;          // m micro-tile index

    float acc[8][8] = {};

    // Prologue: load tile 0 into buffer 0
    {
        float4 a4 = *(const float4*)(Aptr);
        float4 b4 = *(const float4*)(Bptr);
        As[0][lk + 0][lr] = a4.x; As[0][lk + 1][lr] = a4.y;
        As[0][lk + 2][lr] = a4.z; As[0][lk + 3][lr] = a4.w;
        Bs[0][lk + 0][lr] = b4.x; Bs[0][lk + 1][lr] = b4.y;
        Bs[0][lk + 2][lr] = b4.z; Bs[0][lk + 3][lr] = b4.w;
    }
    __syncthreads();

    int buf = 0;
    for (int k0 = 0; k0 < KTOT; k0 += BK) {
        // Prefetch next tile from global while computing current
        float4 a4, b4;
        const bool has_next = (k0 + BK) < KTOT;
        if (has_next) {
            a4 = *(const float4*)(Aptr + k0 + BK);
            b4 = *(const float4*)(Bptr + k0 + BK);
        }

        #pragma unroll
        for (int kk = 0; kk < BK; kk++) {
            float a[8], b[8];
            *(float4*)(a)     = *(const float4*)&As[buf][kk][ty * 8];
            *(float4*)(a + 4) = *(const float4*)&As[buf][kk][ty * 8 + 4];
            *(float4*)(b)     = *(const float4*)&Bs[buf][kk][tx * 8];
            *(float4*)(b + 4) = *(const float4*)&Bs[buf][kk][tx * 8 + 4];
            #pragma unroll
            for (int i = 0; i < 8; i++)
                #pragma unroll
                for (int j = 0; j < 8; j++)
                    acc[i][j] += a[i] * b[j];
        }

        if (has_next) {
            const int nb = buf ^ 1;
            // Writing the other buffer: no conflict with in-flight reads of buf.
            As[nb][lk + 0][lr] = a4.x; As[nb][lk + 1][lr] = a4.y;
            As[nb][lk + 2][lr] = a4.z; As[nb][lk + 3][lr] = a4.w;
            Bs[nb][lk + 0][lr] = b4.x; Bs[nb][lk + 1][lr] = b4.y;
            Bs[nb][lk + 2][lr] = b4.z; Bs[nb][lk + 3][lr] = b4.w;
            __syncthreads();       // single barrier per iteration
            buf = nb;
        }
    }

    #pragma unroll
    for (int i = 0; i < 8; i++) {
        float* crow = C + (size_t)(m0 + ty * 8 + i) * N_OUT + n0 + tx * 8;
        *(float4*)(crow)     = make_float4(acc[i][0], acc[i][1], acc[i][2], acc[i][3]);
        *(float4*)(crow + 4) = make_float4(acc[i][4], acc[i][5], acc[i][6], acc[i][7]);
    }
}

// ---------------------------------------------------------------------------
extern "C" void kernel_launch(void* const* d_in, const int* in_sizes, int n_in,
                              void* d_out, int out_size) {
    const float* x        = (const float*)d_in[0];
    const float* ln_gamma = (const float*)d_in[1];
    const float* ln_beta  = (const float*)d_in[2];
    const float* base_w   = (const float*)d_in[3];
    const float* spline_w = (const float*)d_in[4];
    // d_in[5] = grid, d_in[6] = rbf_grid: uniform, reproduced as fp32 constants.
    (void)in_sizes; (void)n_in; (void)out_size;

    prep_kernel<<<N_OUT, 256>>>(base_w, spline_w);
    feat_kernel<<<M_ROWS, 256>>>(x, ln_gamma, ln_beta);
    dim3 grid(N_OUT / BN, M_ROWS / BM);
    gemm_kernel<<<grid, 256>>>((float*)d_out);
}

// round 5
// speedup vs baseline: 2.7014x; 2.7014x over previous
#include <cuda_runtime.h>
#include <cuda_bf16.h>
#include <cstdint>

// Problem constants
#define M_ROWS 16384      // 8 * 2048
#define D_IN   512
#define NB     8
#define KTOT   4608       // 512 (relu base) + 512*8 (bs+rbf)
#define N_OUT  512

// GEMM tiling (mma.sync path, base compute_100 features only)
#define BM 128
#define BN 64
#define BK 32                       // bf16 K per stage
#define NITER (KTOT / BK)           // 144
#define ASTRIDE 80                  // bytes per smem row: 32 bf16 (64B) + 16B pad
#define A_BYTES (BM * ASTRIDE)      // 10240
#define B_BYTES (BN * ASTRIDE)      // 5120
#define STG_BYTES (2 * A_BYTES + 2 * B_BYTES)   // 30720: Ah | Al | Bh | Bl
#define SMEM_TOTAL (2 * STG_BYTES)              // 61440

// Scratch: bf16 hi/lo split feature + weight matrices
__device__ __nv_bfloat16 g_Fh[(size_t)M_ROWS * KTOT];
__device__ __nv_bfloat16 g_Fl[(size_t)M_ROWS * KTOT];
__device__ __nv_bfloat16 g_Wh[(size_t)N_OUT * KTOT];
__device__ __nv_bfloat16 g_Wl[(size_t)N_OUT * KTOT];

// ---------------------------------------------------------------------------
// PTX helpers — all base sm_80-class features, valid on compute_100
// ---------------------------------------------------------------------------
__device__ __forceinline__ uint32_t smem_u32(const void* p) {
    uint32_t a;
    asm("{ .reg .u64 t; cvta.to.shared.u64 t, %1; cvt.u32.u64 %0, t; }" : "=r"(a) : "l"(p));
    return a;
}
__device__ __forceinline__ void cp_async16(uint32_t s, const void* g) {
    asm volatile("cp.async.cg.shared.global [%0], [%1], 16;" :: "r"(s), "l"(g));
}
#define CP_COMMIT() asm volatile("cp.async.commit_group;" ::: "memory")
#define CP_WAIT(n)  asm volatile("cp.async.wait_group %0;" :: "n"(n) : "memory")

__device__ __forceinline__ void ldsm4(uint32_t* r, uint32_t addr) {
    asm volatile("ldmatrix.sync.aligned.m8n8.x4.shared.b16 {%0,%1,%2,%3}, [%4];"
                 : "=r"(r[0]), "=r"(r[1]), "=r"(r[2]), "=r"(r[3]) : "r"(addr));
}
__device__ __forceinline__ void mma16816(float* c, const uint32_t* a,
                                         uint32_t b0, uint32_t b1) {
    asm volatile("mma.sync.aligned.m16n8k16.row.col.f32.bf16.bf16.f32 "
                 "{%0,%1,%2,%3}, {%4,%5,%6,%7}, {%8,%9}, {%0,%1,%2,%3};"
                 : "+f"(c[0]), "+f"(c[1]), "+f"(c[2]), "+f"(c[3])
                 : "r"(a[0]), "r"(a[1]), "r"(a[2]), "r"(a[3]), "r"(b0), "r"(b1));
}

// ---------------------------------------------------------------------------
// Kernel 0: split weights to bf16 hi/lo, concat [base | spline]
// ---------------------------------------------------------------------------
__global__ void prep_kernel(const float* __restrict__ bw,
                            const float* __restrict__ sw) {
    int o = blockIdx.x;           // 0..511
    int t = threadIdx.x;          // 256 threads
    size_t rb = (size_t)o * KTOT;
    for (int k = t; k < D_IN; k += 256) {
        float v = bw[o * D_IN + k];
        __nv_bfloat16 h = __float2bfloat16(v);
        g_Wh[rb + k] = h;
        g_Wl[rb + k] = __float2bfloat16(v - __bfloat162float(h));
    }
    const float* sp = sw + (size_t)o * (D_IN * NB);
    for (int k = t; k < D_IN * NB; k += 256) {
        float v = sp[k];
        __nv_bfloat16 h = __float2bfloat16(v);
        g_Wh[rb + D_IN + k] = h;
        g_Wl[rb + D_IN + k] = __float2bfloat16(v - __bfloat162float(h));
    }
}

// ---------------------------------------------------------------------------
// Kernel 1: layernorm + features, written as bf16 hi/lo split
// ---------------------------------------------------------------------------
__global__ void feat_kernel(const float* __restrict__ x,
                            const float* __restrict__ gamma,
                            const float* __restrict__ beta) {
    const int row = blockIdx.x;
    const int t   = threadIdx.x;        // 256 threads, 2 dims each
    const float* xr = x + (size_t)row * D_IN;

    float v0 = xr[t];
    float v1 = xr[t + 256];
    float s  = v0 + v1;
    float s2 = v0 * v0 + v1 * v1;
    #pragma unroll
    for (int off = 16; off; off >>= 1) {
        s  += __shfl_xor_sync(0xFFFFFFFFu, s,  off);
        s2 += __shfl_xor_sync(0xFFFFFFFFu, s2, off);
    }
    __shared__ float red[16];
    __shared__ float mu_s, rstd_s;
    int wid = t >> 5, lane = t & 31;
    if (lane == 0) { red[wid] = s; red[8 + wid] = s2; }
    __syncthreads();
    if (t == 0) {
        float ts = 0.f, ts2 = 0.f;
        #pragma unroll
        for (int i = 0; i < 8; i++) { ts += red[i]; ts2 += red[8 + i]; }
        float mu  = ts * (1.0f / 512.0f);
        float var = ts2 * (1.0f / 512.0f) - mu * mu;
        mu_s   = mu;
        rstd_s = rsqrtf(var + 1e-5f);
    }
    __syncthreads();
    const float mu = mu_s, rstd = rstd_s;

    size_t rb = (size_t)row * KTOT;
    const float H    = 3.0f / 5.0f;
    const float INVD = 7.0f / 3.0f;

    #pragma unroll
    for (int half = 0; half < 2; half++) {
        const int   d  = t + half * 256;
        const float xv = half ? v1 : v0;
        const float xn = (xv - mu) * rstd * gamma[d] + beta[d];

        float rl = fmaxf(xn, 0.0f);
        __nv_bfloat16 rh = __float2bfloat16(rl);
        g_Fh[rb + d] = rh;
        g_Fl[rb + d] = __float2bfloat16(rl - __bfloat162float(rh));

        // Cox-de Boor, uniform knots t_i = (i-3)*H - 1.5, i=0..11
        float b[11];
        #pragma unroll
        for (int i = 0; i < 11; i++) {
            float t0 = (float)(i - 3) * H - 1.5f;
            float t1 = (float)(i - 2) * H - 1.5f;
            b[i] = (xn >= t0 && xn < t1) ? 1.0f : 0.0f;
        }
        #pragma unroll
        for (int k = 1; k <= 3; k++) {
            const float inv = 1.0f / ((float)k * H);
            #pragma unroll
            for (int i = 0; i + k < 11; i++) {
                float ti   = (float)(i - 3) * H - 1.5f;
                float tik1 = (float)(i + k - 2) * H - 1.5f;
                float left  = (xn - ti) * inv;
                float right = (tik1 - xn) * inv;
                b[i] = left * b[i] + right * b[i + 1];
            }
        }

        __nv_bfloat16 oh[8], ol[8];
        #pragma unroll
        for (int j = 0; j < 8; j++) {
            float g = -1.5f + (float)j * (3.0f / 7.0f);
            float u = (xn - g) * INVD;
            float f = b[j] + __expf(-u * u);
            __nv_bfloat16 h = __float2bfloat16(f);
            oh[j] = h;
            ol[j] = __float2bfloat16(f - __bfloat162float(h));
        }
        *(uint4*)(&g_Fh[rb + D_IN + (size_t)d * NB]) = *(const uint4*)oh;
        *(uint4*)(&g_Fl[rb + D_IN + (size_t)d * NB]) = *(const uint4*)ol;
    }
}

// ---------------------------------------------------------------------------
// Kernel 2: mma.sync bf16 GEMM with hi/lo compensation
//   C = Fh*Wh^T + Fh*Wl^T + Fl*Wh^T   (fp32 accumulators)
// CTA: 128(M) x 64(N), 4 warps, warp tile 32x64. 2-stage cp.async pipeline.
// ---------------------------------------------------------------------------
__global__ __launch_bounds__(128, 2) void gemm_kernel(float* __restrict__ C) {
    extern __shared__ char smem[];
    const uint32_t sbase = smem_u32(smem);
    const int t    = threadIdx.x;
    const int wm   = t >> 5;            // warp index = m sub-tile (0..3)
    const int lane = t & 31;
    const int m0   = blockIdx.y * BM;
    const int n0   = blockIdx.x * BN;

    const __nv_bfloat16* Ah_g = g_Fh + (size_t)m0 * KTOT;
    const __nv_bfloat16* Al_g = g_Fl + (size_t)m0 * KTOT;
    const __nv_bfloat16* Bh_g = g_Wh + (size_t)n0 * KTOT;
    const __nv_bfloat16* Bl_g = g_Wl + (size_t)n0 * KTOT;

    // Per-lane ldmatrix base offsets
    //   A (x4 over m16 x k16): row=(l>>3 &1)*8 + (l&7), kchunk=(l>>4)*16B
    const uint32_t a_off = (uint32_t)((((lane >> 3) & 1) * 8 + (lane & 7)) * ASTRIDE
                                      + (lane >> 4) * 16);
    //   B (x4 over two n8 blocks x k16): nrow=(l>>4 &1)*8 + (l&7), kchunk=(l>>3 &1)*16B
    const uint32_t b_off = (uint32_t)((((lane >> 4) & 1) * 8 + (lane & 7)) * ASTRIDE
                                      + ((lane >> 3) & 1) * 16);

    float acc[2][8][4];
    #pragma unroll
    for (int i = 0; i < 2; i++)
        #pragma unroll
        for (int j = 0; j < 8; j++)
            #pragma unroll
            for (int q = 0; q < 4; q++) acc[i][j][q] = 0.0f;

    // ---- stage loader: 12 cp.async of 16B per thread ----
    // A tile: 128 rows x 4 chunks = 512 units -> 4 rounds of 128 threads (BUGFIX:
    // previous round only covered 256 units, leaving smem rows 64..127 garbage).
    auto load_stage = [&](int st, int kc) {
        const uint32_t stage = sbase + st * STG_BYTES;
        #pragma unroll
        for (int r = 0; r < 4; r++) {
            int u = t + r * 128;               // 0..511
            int row = u >> 2, ch = u & 3;
            size_t go = (size_t)row * KTOT + kc + ch * 8;
            uint32_t so = (uint32_t)(row * ASTRIDE + ch * 16);
            cp_async16(stage + so,            Ah_g + go);
            cp_async16(stage + A_BYTES + so,  Al_g + go);
        }
        // B tile: 64 rows x 4 chunks = 256 units -> 2 rounds
        #pragma unroll
        for (int r = 0; r < 2; r++) {
            int u = t + r * 128;               // 0..255
            int row = u >> 2, ch = u & 3;
            size_t go = (size_t)row * KTOT + kc + ch * 8;
            uint32_t so = (uint32_t)(row * ASTRIDE + ch * 16);
            cp_async16(stage + 2 * A_BYTES + so,            Bh_g + go);
            cp_async16(stage + 2 * A_BYTES + B_BYTES + so,  Bl_g + go);
        }
    };

    load_stage(0, 0);
    CP_COMMIT();

    for (int i = 0; i < NITER; i++) {
        if (i + 1 < NITER) {
            load_stage((i + 1) & 1, (i + 1) * BK);
            CP_COMMIT();
            CP_WAIT(1);
        } else {
            CP_WAIT(0);
        }
        __syncthreads();

        const uint32_t stage = sbase + (i & 1) * STG_BYTES;
        const uint32_t sAh = stage;
        const uint32_t sAl = stage + A_BYTES;
        const uint32_t sBh = stage + 2 * A_BYTES;
        const uint32_t sBl = stage + 2 * A_BYTES + B_BYTES;
        const uint32_t awarp = (uint32_t)(wm * 32 * ASTRIDE);

        #pragma unroll
        for (int s = 0; s < 2; s++) {       // two k16 steps
            const uint32_t ks = (uint32_t)(s * 32);   // 16 bf16 = 32 bytes
            uint32_t ah[2][4], al[2][4], bh[4][4], bl[4][4];
            #pragma unroll
            for (int im = 0; im < 2; im++) {
                ldsm4(ah[im], sAh + awarp + (uint32_t)(im * 16 * ASTRIDE) + a_off + ks);
                ldsm4(al[im], sAl + awarp + (uint32_t)(im * 16 * ASTRIDE) + a_off + ks);
            }
            #pragma unroll
            for (int jj = 0; jj < 4; jj++) {
                ldsm4(bh[jj], sBh + (uint32_t)(jj * 16 * ASTRIDE) + b_off + ks);
                ldsm4(bl[jj], sBl + (uint32_t)(jj * 16 * ASTRIDE) + b_off + ks);
            }
            #pragma unroll
            for (int im = 0; im < 2; im++)
                #pragma unroll
                for (int j = 0; j < 8; j++) {
                    uint32_t bh0 = bh[j >> 1][(j & 1) * 2];
                    uint32_t bh1 = bh[j >> 1][(j & 1) * 2 + 1];
                    uint32_t bl0 = bl[j >> 1][(j & 1) * 2];
                    uint32_t bl1 = bl[j >> 1][(j & 1) * 2 + 1];
                    mma16816(acc[im][j], ah[im], bh0, bh1);   // hi*hi
                    mma16816(acc[im][j], ah[im], bl0, bl1);   // hi*lo
                    mma16816(acc[im][j], al[im], bh0, bh1);   // lo*hi
                }
        }
        __syncthreads();   // all warps done with this stage before it is refilled
    }

    // Writeout: C row = m0 + wm*32 + im*16 + lane/4 (+8), col = n0 + j*8 + (lane%4)*2
    #pragma unroll
    for (int im = 0; im < 2; im++) {
        int r0 = m0 + wm * 32 + im * 16 + (lane >> 2);
        #pragma unroll
        for (int j = 0; j < 8; j++) {
            int cc = n0 + j * 8 + (lane & 3) * 2;
            *(float2*)(C + (size_t)r0 * N_OUT + cc) =
                make_float2(acc[im][j][0], acc[im][j][1]);
            *(float2*)(C + (size_t)(r0 + 8) * N_OUT + cc) =
                make_float2(acc[im][j][2], acc[im][j][3]);
        }
    }
}

// ---------------------------------------------------------------------------
extern "C" void kernel_launch(void* const* d_in, const int* in_sizes, int n_in,
                              void* d_out, int out_size) {
    const float* x        = (const float*)d_in[0];
    const float* ln_gamma = (const float*)d_in[1];
    const float* ln_beta  = (const float*)d_in[2];
    const float* base_w   = (const float*)d_in[3];
    const float* spline_w = (const float*)d_in[4];
    (void)in_sizes; (void)n_in; (void)out_size;

    cudaFuncSetAttribute(gemm_kernel, cudaFuncAttributeMaxDynamicSharedMemorySize, SMEM_TOTAL);

    prep_kernel<<<N_OUT, 256>>>(base_w, spline_w);
    feat_kernel<<<M_ROWS, 256>>>(x, ln_gamma, ln_beta);
    dim3 grid(N_OUT / BN, M_ROWS / BM);   // (8, 128)
    gemm_kernel<<<grid, 128, SMEM_TOTAL>>>((float*)d_out);
}